// round 11
// baseline (speedup 1.0000x reference)
#include <cuda_runtime.h>
#include <cuda_fp16.h>
#include <cstdint>

#define F_ 32
#define B_ 4096
#define D_ 64
#define K_ 512
#define NTHREADS 256
#define CAP 16

// ---------------- device scratch ----------------
__device__ __half g_wh1[(size_t)F_ * K_ * D_];  // fp16 limb1, [f][k][d]
__device__ __half g_wh2[(size_t)F_ * K_ * D_];  // fp16 limb2, [f][k][d]
__device__ float  g_wn [F_ * K_];               // 0.5*||w_k||^2
__device__ float  g_wmax[F_];                   // max_k ||w_k||
__device__ float  g_partial[1024];
__device__ int    g_count;

__device__ __forceinline__ uint32_t smem_u32(const void* p) {
    uint32_t a;
    asm("{ .reg .u64 t; cvta.to.shared.u64 t, %1; cvt.u32.u64 %0, t; }"
        : "=r"(a) : "l"(p));
    return a;
}

#define LDSM_X4(r_, addr_) \
    asm volatile("ldmatrix.sync.aligned.m8n8.x4.shared.b16 {%0,%1,%2,%3}, [%4];" \
        : "=r"((r_)[0]), "=r"((r_)[1]), "=r"((r_)[2]), "=r"((r_)[3]) : "r"(addr_))

#define CP_ASYNC16(dst_, src_) \
    asm volatile("cp.async.cg.shared.global [%0], [%1], 16;" :: "r"(dst_), "l"(src_))
#define CP_COMMIT() asm volatile("cp.async.commit_group;" ::: "memory")
#define CP_WAIT0()  asm volatile("cp.async.wait_group 0;" ::: "memory")

__device__ __forceinline__ void mma_f16(float* c, const uint32_t* a,
                                        const uint32_t* b) {
    asm volatile(
        "mma.sync.aligned.m16n8k16.row.col.f32.f16.f16.f32 "
        "{%0,%1,%2,%3}, {%4,%5,%6,%7}, {%8,%9}, {%0,%1,%2,%3};"
        : "+f"(c[0]), "+f"(c[1]), "+f"(c[2]), "+f"(c[3])
        : "r"(a[0]), "r"(a[1]), "r"(a[2]), "r"(a[3]), "r"(b[0]), "r"(b[1]));
}

__device__ __forceinline__ uint32_t pack_h2(__half a, __half b) {
    __half2 h = __halves2half2(a, b);
    return *(uint32_t*)&h;
}

// smem (bytes). xs/ws: 128B rows + SW128 XOR: phys = row*128 + (col ^ ((row&7)<<4))
#define OFF_WNS   0        // 512 f32
#define OFF_SIDX  2048     // 128 int
#define OFF_RED8  2560     // 8 f32
#define OFF_RB    2592     // rowbest, 128 f32
#define OFF_MG    3104     // threshold (2m), 128 f32
#define OFF_CNT   3616     // cand counters, 128 int
#define OFF_LIST  4128     // cand lists, 128 x CAP int = 8192
#define OFF_REDV  12320    // per-chunk row reduce, 128x16 f32 = 8192
#define OFF_X1    20608    // x limb1, 16384 (128-aligned)
#define OFF_X2    36992    // x limb2, 16384
#define OFF_WS    53376    // w limb1 chunks, 2 bufs x 8192
#define SMEM_BYTES 69760

// ---------------------------------------------------------------------------
// Prep: transpose + fp16 2-limb split + norms + per-f max norm.
// grid (16, 32) x 256.
// ---------------------------------------------------------------------------
__global__ void vq_prep(const float* __restrict__ w) {
    __shared__ float ts[32][65];
    __shared__ float ps[32][9];
    const int f = blockIdx.y, kt = blockIdx.x, tid = threadIdx.x;
    const float* wf = w + (size_t)f * D_ * K_ + kt * 32;

    for (int i = tid; i < 64 * 32; i += 256) {
        int d = i >> 5, kk = i & 31;
        ts[kk][d] = wf[(size_t)d * K_ + kk];
    }
    __syncthreads();

    size_t base = ((size_t)f * K_ + (size_t)kt * 32) * D_;
    for (int i = tid; i < 32 * 64; i += 256) {
        int kk = i >> 6, d = i & 63;
        float v = ts[kk][d];
        __half h1 = __float2half_rn(v);
        __half h2 = __float2half_rn(v - __half2float(h1));
        g_wh1[base + i] = h1;
        g_wh2[base + i] = h2;
    }
    {
        int kk = tid >> 3, seg = tid & 7;
        float s = 0.f;
#pragma unroll
        for (int d8 = 0; d8 < 8; ++d8) {
            float v = ts[kk][seg * 8 + d8];
            s += v * v;
        }
        ps[kk][seg] = s;
    }
    __syncthreads();
    if (tid < 32) {
        float s = 0.f;
#pragma unroll
        for (int g = 0; g < 8; ++g) s += ps[tid][g];
        g_wn[f * K_ + kt * 32 + tid] = 0.5f * s;
        atomicMax((int*)&g_wmax[f], __float_as_int(sqrtf(s)));
    }
}

// ---------------------------------------------------------------------------
// Main: stage1 = 1-product approx GEMM (h1*w1) + margin-pruned candidates;
// stage2 = exact fp32 rescore of candidates. Fused gather + loss.
// grid (32, 32), 256 thr = 8 warps (2M x 4N), warp tile 64x16.
// ---------------------------------------------------------------------------
__global__ __launch_bounds__(NTHREADS, 3)
void vq_main(const float* __restrict__ x, float* __restrict__ out,
             int loss_pos) {
    extern __shared__ __align__(1024) char smem[];
    const uint32_t sb = smem_u32(smem);
    float* wns   = (float*)(smem + OFF_WNS);
    int*   sidx  = (int*)(smem + OFF_SIDX);
    float* red8  = (float*)(smem + OFF_RED8);
    float* rowbest = (float*)(smem + OFF_RB);
    float* marg  = (float*)(smem + OFF_MG);
    int*   cnt   = (int*)(smem + OFF_CNT);
    int*   list  = (int*)(smem + OFF_LIST);
    float* red_v = (float*)(smem + OFF_REDV);

    const int f   = blockIdx.y;
    const int b0  = blockIdx.x * 128;
    const int tid = threadIdx.x;
    const int wid = tid >> 5;
    const int lane = tid & 31;
    const int tq = lane >> 2, tr = lane & 3;
    const int wm = wid >> 2,  wn = wid & 3;
    const int lq = lane & 7,  quad = lane >> 3;
    const uint32_t xorv = (uint32_t)lq << 4;

    const __half* wh1g = g_wh1 + ((size_t)f << 9) * D_;
    const __half* wh2g = g_wh2 + ((size_t)f << 9) * D_;
    const float Wf = g_wmax[f];

    // ---- prologue: cp.async chunk 0 (codes 0..63, limb1 only) ----
    {
#pragma unroll
        for (int t = 0; t < 2; ++t) {
            int i = tid + t * 256;              // [0,512)
            int n  = i >> 3;
            int ch = i & 7;
            uint32_t dst = sb + OFF_WS + (uint32_t)n * 128
                         + (((uint32_t)ch * 16) ^ ((uint32_t)(n & 7) << 4));
            CP_ASYNC16(dst, wh1g + (size_t)n * 64 + ch * 8);
        }
        CP_COMMIT();
    }

    wns[tid]       = g_wn[(f << 9) + tid];
    wns[tid + 256] = g_wn[(f << 9) + tid + 256];
    if (tid < 128) { marg[tid] = 0.f; cnt[tid] = 0; rowbest[tid] = -1e30f; }
    __syncthreads();

    // ---- x tile -> fp16 limbs (swizzled) + per-row sumsq ----
    const float* xg = x + ((size_t)f * B_ + b0) * D_;
#pragma unroll
    for (int t = 0; t < 8; ++t) {
        int i = tid + t * 256;
        int r = i >> 4, c4 = i & 15;
        float4 v = ((const float4*)(xg + (size_t)r * D_))[c4];
        __half h1[4], h2[4];
        float vv[4] = {v.x, v.y, v.z, v.w};
#pragma unroll
        for (int j = 0; j < 4; ++j) {
            h1[j] = __float2half_rn(vv[j]);
            h2[j] = __float2half_rn(vv[j] - __half2float(h1[j]));
        }
        atomicAdd(&marg[r], vv[0]*vv[0] + vv[1]*vv[1] + vv[2]*vv[2] + vv[3]*vv[3]);
        uint32_t off = (uint32_t)r * 128
                     + (((uint32_t)c4 * 8) ^ ((uint32_t)(r & 7) << 4));
        *(uint2*)(smem + OFF_X1 + off) =
            make_uint2(pack_h2(h1[0], h1[1]), pack_h2(h1[2], h1[3]));
        *(uint2*)(smem + OFF_X2 + off) =
            make_uint2(pack_h2(h2[0], h2[1]), pack_h2(h2[2], h2[3]));
    }
    __syncthreads();
    if (tid < 128)   // threshold = 2m (+slack): covers |x.w - h1.w1| two-sided
        marg[tid] = 2.06e-3f * sqrtf(marg[tid]) * Wf + 2e-4f;

    const uint32_t aBase = sb + OFF_X1
        + (uint32_t)(wm * 64 + lq + ((quad & 1) << 3)) * 128;
    const uint32_t aColBase = (uint32_t)((quad >> 1) << 4);
    const uint32_t bRowOff = (uint32_t)(wn * 16 + lq) * 128;
    const uint32_t bColBase = (uint32_t)quad * 16;

    for (int c = 0; c < 8; ++c) {
        CP_WAIT0();
        __syncthreads();

        if (c < 7) {
            int cn = c + 1;
            uint32_t bufoff = (uint32_t)(cn & 1) * 8192;
#pragma unroll
            for (int t = 0; t < 2; ++t) {
                int i = tid + t * 256;
                int n  = i >> 3;
                int ch = i & 7;
                uint32_t dst = sb + OFF_WS + bufoff + (uint32_t)n * 128
                             + (((uint32_t)ch * 16) ^ ((uint32_t)(n & 7) << 4));
                CP_ASYNC16(dst, wh1g + ((size_t)(cn * 64 + n)) * 64 + ch * 8);
            }
            CP_COMMIT();
        }

        const uint32_t wsb = sb + OFF_WS + (uint32_t)(c & 1) * 8192;

        float acc[4][2][4];
#pragma unroll
        for (int i = 0; i < 4; ++i)
#pragma unroll
            for (int j = 0; j < 2; ++j)
#pragma unroll
                for (int q = 0; q < 4; ++q) acc[i][j][q] = 0.f;

#pragma unroll
        for (int kkp = 0; kkp < 2; ++kkp) {
            uint32_t bb1[2][4];
#pragma unroll
            for (int j = 0; j < 2; ++j) {
                uint32_t ba = wsb + bRowOff + (uint32_t)j * 1024
                            + ((bColBase + (uint32_t)kkp * 64) ^ xorv);
                LDSM_X4(bb1[j], ba);
            }
#pragma unroll
            for (int kk2 = 0; kk2 < 2; ++kk2) {
                const int kreg = kk2 * 2;
                const uint32_t kcol = (uint32_t)(kkp * 2 + kk2) * 32;
#pragma unroll
                for (int i = 0; i < 4; ++i) {
                    uint32_t aa = aBase + (uint32_t)i * 2048
                                + ((aColBase + kcol) ^ xorv);
                    uint32_t a1[4];
                    LDSM_X4(a1, aa);
#pragma unroll
                    for (int j = 0; j < 2; ++j)
                        mma_f16(acc[i][j], a1, bb1[j] + kreg);   // h1*w1 only
                }
            }
        }

        // chunk fold 1: per-thread local max per row -> red_v
#pragma unroll
        for (int i = 0; i < 4; ++i)
#pragma unroll
            for (int h = 0; h < 2; ++h) {
                float lm = -1e30f;
#pragma unroll
                for (int j = 0; j < 2; ++j)
#pragma unroll
                    for (int c01 = 0; c01 < 2; ++c01) {
                        int kg = c * 64 + wn * 16 + j * 8 + tr * 2 + c01;
                        float s = acc[i][j][h * 2 + c01] - wns[kg];
                        if (s > lm) lm = s;
                    }
                int row = wm * 64 + i * 16 + h * 8 + tq;
                red_v[row * 16 + wn * 4 + tr] = lm;
            }
        __syncthreads();

        // chunk fold 2: update running row max
        if (tid < 128) {
            float m = rowbest[tid];
#pragma unroll
            for (int t2 = 0; t2 < 16; ++t2) m = fmaxf(m, red_v[tid * 16 + t2]);
            rowbest[tid] = m;
        }
        __syncthreads();

        // chunk fold 3: append margin candidates (deterministic set)
#pragma unroll
        for (int i = 0; i < 4; ++i)
#pragma unroll
            for (int h = 0; h < 2; ++h) {
                int row = wm * 64 + i * 16 + h * 8 + tq;
                float thr = rowbest[row] - marg[row];
#pragma unroll
                for (int j = 0; j < 2; ++j)
#pragma unroll
                    for (int c01 = 0; c01 < 2; ++c01) {
                        int kg = c * 64 + wn * 16 + j * 8 + tr * 2 + c01;
                        float s = acc[i][j][h * 2 + c01] - wns[kg];
                        if (s >= thr) {
                            int p = atomicAdd(&cnt[row], 1);
                            if (p < CAP) list[row * CAP + p] = kg;
                        }
                    }
            }
    }
    __syncthreads();

    // ---- stage 2: exact fp32 rescore of candidates ----
    if (tid < 128) {
        const int row = tid;
        const uint32_t xorr = (uint32_t)(row & 7) << 4;
        const int n = cnt[row];
        float bs = -1e30f;
        int bk = 0x7FFFFFFF;
        const int nk = (n <= CAP) ? n : K_;
        for (int p = 0; p < nk; ++p) {
            int k = (n <= CAP) ? list[row * CAP + p] : p;   // fallback: full scan
            float s = 0.f;
            const __half2* w1p = (const __half2*)(wh1g + (size_t)k * 64);
            const __half2* w2p = (const __half2*)(wh2g + (size_t)k * 64);
#pragma unroll 8
            for (int d2 = 0; d2 < 32; ++d2) {
                uint32_t off = (uint32_t)row * 128 + (((uint32_t)d2 * 4) ^ xorr);
                float2 x1 = __half22float2(*(__half2*)(smem + OFF_X1 + off));
                float2 x2 = __half22float2(*(__half2*)(smem + OFF_X2 + off));
                float2 w1 = __half22float2(w1p[d2]);
                float2 w2 = __half22float2(w2p[d2]);
                s += (x1.x + x2.x) * (w1.x + w2.x)
                   + (x1.y + x2.y) * (w1.y + w2.y);
            }
            s -= wns[k];
            if (s > bs || (s == bs && k < bk)) { bs = s; bk = k; }
        }
        sidx[row] = bk;
    }
    __syncthreads();

    // ---- gather (q = h1 + h2) + loss ----
    float lsum = 0.f;
    float* og = out + ((size_t)f * B_ + b0) * D_;
    for (int e = tid; e < 128 * D_; e += NTHREADS) {
        int r = e >> 6, d = e & 63;
        size_t gi = (size_t)sidx[r] * D_ + d;
        float q  = __half2float(wh1g[gi]) + __half2float(wh2g[gi]);
        float xv = xg[e];
        og[e] = q;
        float dif = q - xv;
        lsum += dif * dif;
    }
#pragma unroll
    for (int o = 16; o > 0; o >>= 1)
        lsum += __shfl_xor_sync(0xFFFFFFFFu, lsum, o);
    if ((tid & 31) == 0) red8[wid] = lsum;
    __syncthreads();

    __shared__ int s_last;
    if (tid == 0) {
        float t = 0.f;
#pragma unroll
        for (int i = 0; i < 8; ++i) t += red8[i];
        g_partial[blockIdx.y * gridDim.x + blockIdx.x] = t;
        __threadfence();
        int old = atomicAdd(&g_count, 1);
        s_last = (old == 1023) ? 1 : 0;
    }
    __syncthreads();

    if (s_last) {
        float s = 0.f;
#pragma unroll
        for (int t = 0; t < 4; ++t) s += g_partial[tid + t * 256];
#pragma unroll
        for (int o = 16; o > 0; o >>= 1)
            s += __shfl_xor_sync(0xFFFFFFFFu, s, o);
        if ((tid & 31) == 0) red8[wid] = s;
        __syncthreads();
        if (tid == 0) {
            float t = 0.f;
#pragma unroll
            for (int i = 0; i < 8; ++i) t += red8[i];
            out[loss_pos] = t * (1.25f / (float)(F_ * B_ * D_));
            g_count = 0;
        }
    }
}

// ---------------------------------------------------------------------------
extern "C" void kernel_launch(void* const* d_in, const int* in_sizes, int n_in,
                              void* d_out, int out_size) {
    const float* x = (const float*)d_in[0];   // (F,B,D)
    const float* w = (const float*)d_in[1];   // (F,D,K)
    float* out = (float*)d_out;

    cudaFuncSetAttribute(vq_main, cudaFuncAttributeMaxDynamicSharedMemorySize,
                         SMEM_BYTES);

    dim3 pgrid(16, 32);
    vq_prep<<<pgrid, 256>>>(w);

    dim3 grid(B_ / 128, F_);
    vq_main<<<grid, NTHREADS, SMEM_BYTES>>>(x, out, out_size - 1);
}

// round 12
// speedup vs baseline: 1.0330x; 1.0330x over previous
#include <cuda_runtime.h>
#include <cuda_fp16.h>
#include <cstdint>

#define F_ 32
#define B_ 4096
#define D_ 64
#define K_ 512
#define NTHREADS 256
#define CAP 32

// ---------------- device scratch ----------------
__device__ __half g_wh1[(size_t)F_ * K_ * D_];  // fp16 limb1, [f][k][d]
__device__ __half g_wh2[(size_t)F_ * K_ * D_];  // fp16 limb2, [f][k][d]
__device__ float  g_wn [F_ * K_];               // 0.5*||w_k||^2
__device__ float  g_wmax[F_];                   // max_k ||w_k||
__device__ float  g_partial[1024];
__device__ int    g_count;

__device__ __forceinline__ uint32_t smem_u32(const void* p) {
    uint32_t a;
    asm("{ .reg .u64 t; cvta.to.shared.u64 t, %1; cvt.u32.u64 %0, t; }"
        : "=r"(a) : "l"(p));
    return a;
}

#define LDSM_X4(r_, addr_) \
    asm volatile("ldmatrix.sync.aligned.m8n8.x4.shared.b16 {%0,%1,%2,%3}, [%4];" \
        : "=r"((r_)[0]), "=r"((r_)[1]), "=r"((r_)[2]), "=r"((r_)[3]) : "r"(addr_))

#define CP_ASYNC16(dst_, src_) \
    asm volatile("cp.async.cg.shared.global [%0], [%1], 16;" :: "r"(dst_), "l"(src_))
#define CP_COMMIT() asm volatile("cp.async.commit_group;" ::: "memory")
#define CP_WAIT0()  asm volatile("cp.async.wait_group 0;" ::: "memory")

__device__ __forceinline__ void mma_f16(float* c, const uint32_t* a,
                                        const uint32_t* b) {
    asm volatile(
        "mma.sync.aligned.m16n8k16.row.col.f32.f16.f16.f32 "
        "{%0,%1,%2,%3}, {%4,%5,%6,%7}, {%8,%9}, {%0,%1,%2,%3};"
        : "+f"(c[0]), "+f"(c[1]), "+f"(c[2]), "+f"(c[3])
        : "r"(a[0]), "r"(a[1]), "r"(a[2]), "r"(a[3]), "r"(b[0]), "r"(b[1]));
}

__device__ __forceinline__ uint32_t pack_h2(__half a, __half b) {
    __half2 h = __halves2half2(a, b);
    return *(uint32_t*)&h;
}

// order-preserving float <-> uint key (for smem atomicMax)
__device__ __forceinline__ uint32_t fkey(float v) {
    int i = __float_as_int(v);
    return (i >= 0) ? ((uint32_t)i | 0x80000000u) : (uint32_t)(~i);
}
__device__ __forceinline__ float funkey(uint32_t k) {
    int i = (k & 0x80000000u) ? (int)(k & 0x7FFFFFFFu) : ~(int)k;
    return __int_as_float(i);
}

// smem (bytes). xs/ws: 128B rows + SW128 XOR: phys = row*128 + (col ^ ((row&7)<<4))
#define OFF_WNS   0        // 512 f32
#define OFF_RBK   2048     // rowbest keys, 128 uint
#define OFF_MG    2560     // margin, 128 f32
#define OFF_CNT   3072     // cand counters, 128 int
#define OFF_SIDX  3584     // 128 int
#define OFF_RED8  4096     // 8 f32
#define OFF_LIST  4128     // cand lists, 128 x CAP int = 16384
#define OFF_X1    20608    // x limb1, 16384 (128-aligned)
#define OFF_X2    36992    // x limb2, 16384
#define OFF_WS    53376    // w limb1 chunks, 2 bufs x 8192
#define SMEM_BYTES 69760

// ---------------------------------------------------------------------------
// Prep: transpose + fp16 2-limb split + norms + per-f max norm.
// ---------------------------------------------------------------------------
__global__ void vq_prep(const float* __restrict__ w) {
    __shared__ float ts[32][65];
    __shared__ float ps[32][9];
    const int f = blockIdx.y, kt = blockIdx.x, tid = threadIdx.x;
    const float* wf = w + (size_t)f * D_ * K_ + kt * 32;

    for (int i = tid; i < 64 * 32; i += 256) {
        int d = i >> 5, kk = i & 31;
        ts[kk][d] = wf[(size_t)d * K_ + kk];
    }
    __syncthreads();

    size_t base = ((size_t)f * K_ + (size_t)kt * 32) * D_;
    for (int i = tid; i < 32 * 64; i += 256) {
        int kk = i >> 6, d = i & 63;
        float v = ts[kk][d];
        __half h1 = __float2half_rn(v);
        __half h2 = __float2half_rn(v - __half2float(h1));
        g_wh1[base + i] = h1;
        g_wh2[base + i] = h2;
    }
    {
        int kk = tid >> 3, seg = tid & 7;
        float s = 0.f;
#pragma unroll
        for (int d8 = 0; d8 < 8; ++d8) {
            float v = ts[kk][seg * 8 + d8];
            s += v * v;
        }
        ps[kk][seg] = s;
    }
    __syncthreads();
    if (tid < 32) {
        float s = 0.f;
#pragma unroll
        for (int g = 0; g < 8; ++g) s += ps[tid][g];
        g_wn[f * K_ + kt * 32 + tid] = 0.5f * s;
        atomicMax((int*)&g_wmax[f], __float_as_int(sqrtf(s)));
    }
}

// ---------------------------------------------------------------------------
// Main: stage1 = h1*w1 approx GEMM + margin-pruned candidate lists
//       stage2 = exact fp32 rescore of candidates. Fused gather + loss.
// grid (32, 32), 256 thr = 8 warps (2M x 4N), warp tile 64x16.
// ---------------------------------------------------------------------------
__global__ __launch_bounds__(NTHREADS, 3)
void vq_main(const float* __restrict__ x, float* __restrict__ out,
             int loss_pos) {
    extern __shared__ __align__(1024) char smem[];
    const uint32_t sb = smem_u32(smem);
    float*    wns  = (float*)(smem + OFF_WNS);
    uint32_t* rbk  = (uint32_t*)(smem + OFF_RBK);
    float*    marg = (float*)(smem + OFF_MG);
    int*      cnt  = (int*)(smem + OFF_CNT);
    int*      sidx = (int*)(smem + OFF_SIDX);
    float*    red8 = (float*)(smem + OFF_RED8);
    int*      list = (int*)(smem + OFF_LIST);

    const int f   = blockIdx.y;
    const int b0  = blockIdx.x * 128;
    const int tid = threadIdx.x;
    const int wid = tid >> 5;
    const int lane = tid & 31;
    const int tq = lane >> 2, tr = lane & 3;
    const int wm = wid >> 2,  wn = wid & 3;
    const int lq = lane & 7,  quad = lane >> 3;
    const uint32_t xorv = (uint32_t)lq << 4;

    const __half* wh1g = g_wh1 + ((size_t)f << 9) * D_;
    const __half* wh2g = g_wh2 + ((size_t)f << 9) * D_;
    const float Wf = g_wmax[f];

    // ---- prologue: cp.async chunk 0 (codes 0..63, limb1 only) ----
    {
#pragma unroll
        for (int t = 0; t < 2; ++t) {
            int i = tid + t * 256;
            int n  = i >> 3;
            int ch = i & 7;
            uint32_t dst = sb + OFF_WS + (uint32_t)n * 128
                         + (((uint32_t)ch * 16) ^ ((uint32_t)(n & 7) << 4));
            CP_ASYNC16(dst, wh1g + (size_t)n * 64 + ch * 8);
        }
        CP_COMMIT();
    }

    wns[tid]       = g_wn[(f << 9) + tid];
    wns[tid + 256] = g_wn[(f << 9) + tid + 256];
    if (tid < 128) { marg[tid] = 0.f; cnt[tid] = 0; rbk[tid] = 0u; }
    __syncthreads();

    // ---- x tile -> fp16 limbs (swizzled) + per-row sumsq ----
    const float* xg = x + ((size_t)f * B_ + b0) * D_;
#pragma unroll
    for (int t = 0; t < 8; ++t) {
        int i = tid + t * 256;
        int r = i >> 4, c4 = i & 15;
        float4 v = ((const float4*)(xg + (size_t)r * D_))[c4];
        __half h1[4], h2[4];
        float vv[4] = {v.x, v.y, v.z, v.w};
#pragma unroll
        for (int j = 0; j < 4; ++j) {
            h1[j] = __float2half_rn(vv[j]);
            h2[j] = __float2half_rn(vv[j] - __half2float(h1[j]));
        }
        atomicAdd(&marg[r], vv[0]*vv[0] + vv[1]*vv[1] + vv[2]*vv[2] + vv[3]*vv[3]);
        uint32_t off = (uint32_t)r * 128
                     + (((uint32_t)c4 * 8) ^ ((uint32_t)(r & 7) << 4));
        *(uint2*)(smem + OFF_X1 + off) =
            make_uint2(pack_h2(h1[0], h1[1]), pack_h2(h1[2], h1[3]));
        *(uint2*)(smem + OFF_X2 + off) =
            make_uint2(pack_h2(h2[0], h2[1]), pack_h2(h2[2], h2[3]));
    }
    __syncthreads();
    if (tid < 128)   // threshold margin >= 2m (rigorous superset)
        marg[tid] = 2.06e-3f * sqrtf(marg[tid]) * Wf + 2e-4f;
    __syncthreads();

    const uint32_t aBase = sb + OFF_X1
        + (uint32_t)(wm * 64 + lq + ((quad & 1) << 3)) * 128;
    const uint32_t aColBase = (uint32_t)((quad >> 1) << 4);
    const uint32_t bRowOff = (uint32_t)(wn * 16 + lq) * 128;
    const uint32_t bColBase = (uint32_t)quad * 16;

    for (int c = 0; c < 8; ++c) {
        CP_WAIT0();
        __syncthreads();

        if (c < 7) {
            int cn = c + 1;
            uint32_t bufoff = (uint32_t)(cn & 1) * 8192;
#pragma unroll
            for (int t = 0; t < 2; ++t) {
                int i = tid + t * 256;
                int n  = i >> 3;
                int ch = i & 7;
                uint32_t dst = sb + OFF_WS + bufoff + (uint32_t)n * 128
                             + (((uint32_t)ch * 16) ^ ((uint32_t)(n & 7) << 4));
                CP_ASYNC16(dst, wh1g + ((size_t)(cn * 64 + n)) * 64 + ch * 8);
            }
            CP_COMMIT();
        }

        const uint32_t wsb = sb + OFF_WS + (uint32_t)(c & 1) * 8192;

        float acc[4][2][4];
#pragma unroll
        for (int i = 0; i < 4; ++i)
#pragma unroll
            for (int j = 0; j < 2; ++j)
#pragma unroll
                for (int q = 0; q < 4; ++q) acc[i][j][q] = 0.f;

#pragma unroll
        for (int kkp = 0; kkp < 2; ++kkp) {
            uint32_t bb1[2][4];
#pragma unroll
            for (int j = 0; j < 2; ++j) {
                uint32_t ba = wsb + bRowOff + (uint32_t)j * 1024
                            + ((bColBase + (uint32_t)kkp * 64) ^ xorv);
                LDSM_X4(bb1[j], ba);
            }
#pragma unroll
            for (int kk2 = 0; kk2 < 2; ++kk2) {
                const int kreg = kk2 * 2;
                const uint32_t kcol = (uint32_t)(kkp * 2 + kk2) * 32;
#pragma unroll
                for (int i = 0; i < 4; ++i) {
                    uint32_t aa = aBase + (uint32_t)i * 2048
                                + ((aColBase + kcol) ^ xorv);
                    uint32_t a1[4];
                    LDSM_X4(a1, aa);
#pragma unroll
                    for (int j = 0; j < 2; ++j)
                        mma_f16(acc[i][j], a1, bb1[j] + kreg);   // h1*w1 only
                }
            }
        }

        // fold A: per-thread local max per row-slot -> one atomicMax each
#pragma unroll
        for (int i = 0; i < 4; ++i)
#pragma unroll
            for (int h = 0; h < 2; ++h) {
                float lm = -1e30f;
#pragma unroll
                for (int j = 0; j < 2; ++j)
#pragma unroll
                    for (int c01 = 0; c01 < 2; ++c01) {
                        float s = acc[i][j][h * 2 + c01]
                                - wns[c * 64 + wn * 16 + j * 8 + tr * 2 + c01];
                        lm = fmaxf(lm, s);
                    }
                int row = wm * 64 + i * 16 + h * 8 + tq;
                atomicMax(&rbk[row], fkey(lm));
            }
        __syncthreads();

        // fold B: append margin candidates
#pragma unroll
        for (int i = 0; i < 4; ++i)
#pragma unroll
            for (int h = 0; h < 2; ++h) {
                int row = wm * 64 + i * 16 + h * 8 + tq;
                float thr = funkey(rbk[row]) - marg[row];
#pragma unroll
                for (int j = 0; j < 2; ++j)
#pragma unroll
                    for (int c01 = 0; c01 < 2; ++c01) {
                        int kg = c * 64 + wn * 16 + j * 8 + tr * 2 + c01;
                        float s = acc[i][j][h * 2 + c01] - wns[kg];
                        if (s >= thr) {
                            int p = atomicAdd(&cnt[row], 1);
                            if (p < CAP) list[row * CAP + p] = kg;
                        }
                    }
            }
    }
    __syncthreads();

    // ---- stage 2: exact fp32 rescore of candidates ----
    if (tid < 128) {
        const int row = tid;
        const uint32_t xorr = (uint32_t)(row & 7) << 4;
        const int n = cnt[row];
        float bs = -1e30f;
        int bk = 0x7FFFFFFF;
        const int nk = (n <= CAP) ? n : K_;
        for (int p = 0; p < nk; ++p) {
            int k = (n <= CAP) ? list[row * CAP + p] : p;   // fallback: full scan
            float s = 0.f;
            const __half2* w1p = (const __half2*)(wh1g + (size_t)k * 64);
            const __half2* w2p = (const __half2*)(wh2g + (size_t)k * 64);
#pragma unroll 8
            for (int d2 = 0; d2 < 32; ++d2) {
                uint32_t off = (uint32_t)row * 128 + (((uint32_t)d2 * 4) ^ xorr);
                float2 x1 = __half22float2(*(__half2*)(smem + OFF_X1 + off));
                float2 x2 = __half22float2(*(__half2*)(smem + OFF_X2 + off));
                float2 w1 = __half22float2(w1p[d2]);
                float2 w2 = __half22float2(w2p[d2]);
                s += (x1.x + x2.x) * (w1.x + w2.x)
                   + (x1.y + x2.y) * (w1.y + w2.y);
            }
            s -= wns[k];
            if (s > bs || (s == bs && k < bk)) { bs = s; bk = k; }
        }
        sidx[row] = bk;
    }
    __syncthreads();

    // ---- gather (q = h1 + h2) + loss ----
    float lsum = 0.f;
    float* og = out + ((size_t)f * B_ + b0) * D_;
    for (int e = tid; e < 128 * D_; e += NTHREADS) {
        int r = e >> 6, d = e & 63;
        size_t gi = (size_t)sidx[r] * D_ + d;
        float q  = __half2float(wh1g[gi]) + __half2float(wh2g[gi]);
        float xv = xg[e];
        og[e] = q;
        float dif = q - xv;
        lsum += dif * dif;
    }
#pragma unroll
    for (int o = 16; o > 0; o >>= 1)
        lsum += __shfl_xor_sync(0xFFFFFFFFu, lsum, o);
    if ((tid & 31) == 0) red8[wid] = lsum;
    __syncthreads();

    __shared__ int s_last;
    if (tid == 0) {
        float t = 0.f;
#pragma unroll
        for (int i = 0; i < 8; ++i) t += red8[i];
        g_partial[blockIdx.y * gridDim.x + blockIdx.x] = t;
        __threadfence();
        int old = atomicAdd(&g_count, 1);
        s_last = (old == 1023) ? 1 : 0;
    }
    __syncthreads();

    if (s_last) {
        float s = 0.f;
#pragma unroll
        for (int t = 0; t < 4; ++t) s += g_partial[tid + t * 256];
#pragma unroll
        for (int o = 16; o > 0; o >>= 1)
            s += __shfl_xor_sync(0xFFFFFFFFu, s, o);
        if ((tid & 31) == 0) red8[wid] = s;
        __syncthreads();
        if (tid == 0) {
            float t = 0.f;
#pragma unroll
            for (int i = 0; i < 8; ++i) t += red8[i];
            out[loss_pos] = t * (1.25f / (float)(F_ * B_ * D_));
            g_count = 0;
        }
    }
}

// ---------------------------------------------------------------------------
extern "C" void kernel_launch(void* const* d_in, const int* in_sizes, int n_in,
                              void* d_out, int out_size) {
    const float* x = (const float*)d_in[0];   // (F,B,D)
    const float* w = (const float*)d_in[1];   // (F,D,K)
    float* out = (float*)d_out;

    cudaFuncSetAttribute(vq_main, cudaFuncAttributeMaxDynamicSharedMemorySize,
                         SMEM_BYTES);

    dim3 pgrid(16, 32);
    vq_prep<<<pgrid, 256>>>(w);

    dim3 grid(B_ / 128, F_);
    vq_main<<<grid, NTHREADS, SMEM_BYTES>>>(x, out, out_size - 1);
}

// round 13
// speedup vs baseline: 1.0677x; 1.0336x over previous
#include <cuda_runtime.h>
#include <cuda_fp16.h>
#include <cstdint>

#define F_ 32
#define B_ 4096
#define D_ 64
#define K_ 512
#define NTHREADS 256

// ---------------- device scratch ----------------
__device__ __half g_wh1[(size_t)F_ * K_ * D_];  // fp16 limb1, [f][k][d]
__device__ __half g_wh2[(size_t)F_ * K_ * D_];  // fp16 limb2, [f][k][d]
__device__ float  g_wn [F_ * K_];               // 0.5*||w_k||^2
__device__ float  g_wmax[F_];                   // max_k ||w_k||
__device__ float  g_partial[1024];
__device__ int    g_count;

__device__ __forceinline__ uint32_t smem_u32(const void* p) {
    uint32_t a;
    asm("{ .reg .u64 t; cvta.to.shared.u64 t, %1; cvt.u32.u64 %0, t; }"
        : "=r"(a) : "l"(p));
    return a;
}

#define LDSM_X4(r_, addr_) \
    asm volatile("ldmatrix.sync.aligned.m8n8.x4.shared.b16 {%0,%1,%2,%3}, [%4];" \
        : "=r"((r_)[0]), "=r"((r_)[1]), "=r"((r_)[2]), "=r"((r_)[3]) : "r"(addr_))

#define CP_ASYNC16(dst_, src_) \
    asm volatile("cp.async.cg.shared.global [%0], [%1], 16;" :: "r"(dst_), "l"(src_))
#define CP_COMMIT() asm volatile("cp.async.commit_group;" ::: "memory")
#define CP_WAIT0()  asm volatile("cp.async.wait_group 0;" ::: "memory")

__device__ __forceinline__ void mma_f16(float* c, const uint32_t* a,
                                        const uint32_t* b) {
    asm volatile(
        "mma.sync.aligned.m16n8k16.row.col.f32.f16.f16.f32 "
        "{%0,%1,%2,%3}, {%4,%5,%6,%7}, {%8,%9}, {%0,%1,%2,%3};"
        : "+f"(c[0]), "+f"(c[1]), "+f"(c[2]), "+f"(c[3])
        : "r"(a[0]), "r"(a[1]), "r"(a[2]), "r"(a[3]), "r"(b[0]), "r"(b[1]));
}

__device__ __forceinline__ uint32_t pack_h2(__half a, __half b) {
    __half2 h = __halves2half2(a, b);
    return *(uint32_t*)&h;
}

// order-preserving float <-> uint key (for smem atomicMax)
__device__ __forceinline__ uint32_t fkey(float v) {
    int i = __float_as_int(v);
    return (i >= 0) ? ((uint32_t)i | 0x80000000u) : (uint32_t)(~i);
}
__device__ __forceinline__ float funkey(uint32_t k) {
    int i = (k & 0x80000000u) ? (int)(k & 0x7FFFFFFFu) : ~(int)k;
    return __int_as_float(i);
}

// smem (bytes). xs/ws: 128B rows + SW128 XOR: phys = row*128 + (col ^ ((row&7)<<4))
#define OFF_WNS   0        // 512 f32 (2048)
#define OFF_RBK   2048     // rowbest keys, 128 uint (512)
#define OFF_MG    2560     // margin, 128 f32 (512)
#define OFF_SIDX  3072     // 128 int (512)
#define OFF_RED8  3584     // 8 f32 (32)
#define OFF_BS2   3616     // stage2 partial best score, 256 f32 (1024)
#define OFF_BK2   4640     // stage2 partial best idx, 256 int (1024)
#define OFF_MASK  5664     // cand bitmask, 128 x 16 uint (8192)
#define OFF_X1    13952    // x limb1, 16384 (128-aligned)
#define OFF_X2    30336    // x limb2, 16384
#define OFF_WS    46720    // w limb1 chunks, 2 bufs x 8192
#define SMEM_BYTES 63488

// ---------------------------------------------------------------------------
// Prep: transpose + fp16 2-limb split + norms + per-f max norm.
// ---------------------------------------------------------------------------
__global__ void vq_prep(const float* __restrict__ w) {
    __shared__ float ts[32][65];
    __shared__ float ps[32][9];
    const int f = blockIdx.y, kt = blockIdx.x, tid = threadIdx.x;
    const float* wf = w + (size_t)f * D_ * K_ + kt * 32;

    for (int i = tid; i < 64 * 32; i += 256) {
        int d = i >> 5, kk = i & 31;
        ts[kk][d] = wf[(size_t)d * K_ + kk];
    }
    __syncthreads();

    size_t base = ((size_t)f * K_ + (size_t)kt * 32) * D_;
    for (int i = tid; i < 32 * 64; i += 256) {
        int kk = i >> 6, d = i & 63;
        float v = ts[kk][d];
        __half h1 = __float2half_rn(v);
        __half h2 = __float2half_rn(v - __half2float(h1));
        g_wh1[base + i] = h1;
        g_wh2[base + i] = h2;
    }
    {
        int kk = tid >> 3, seg = tid & 7;
        float s = 0.f;
#pragma unroll
        for (int d8 = 0; d8 < 8; ++d8) {
            float v = ts[kk][seg * 8 + d8];
            s += v * v;
        }
        ps[kk][seg] = s;
    }
    __syncthreads();
    if (tid < 32) {
        float s = 0.f;
#pragma unroll
        for (int g = 0; g < 8; ++g) s += ps[tid][g];
        g_wn[f * K_ + kt * 32 + tid] = 0.5f * s;
        atomicMax((int*)&g_wmax[f], __float_as_int(sqrtf(s)));
    }
}

// ---------------------------------------------------------------------------
// Main: stage1 = h1*w1 approx GEMM + margin-pruned candidate BITMASK (no cap,
// no fallback); stage2 = parallel exact fp32 rescore. Fused gather + loss.
// grid (32, 32), 256 thr = 8 warps (2M x 4N), warp tile 64x16.
// ---------------------------------------------------------------------------
__global__ __launch_bounds__(NTHREADS, 3)
void vq_main(const float* __restrict__ x, float* __restrict__ out,
             int loss_pos) {
    extern __shared__ __align__(1024) char smem[];
    const uint32_t sb = smem_u32(smem);
    float*    wns  = (float*)(smem + OFF_WNS);
    uint32_t* rbk  = (uint32_t*)(smem + OFF_RBK);
    float*    marg = (float*)(smem + OFF_MG);
    int*      sidx = (int*)(smem + OFF_SIDX);
    float*    red8 = (float*)(smem + OFF_RED8);
    float*    bs2  = (float*)(smem + OFF_BS2);
    int*      bk2  = (int*)(smem + OFF_BK2);
    uint32_t* mask = (uint32_t*)(smem + OFF_MASK);

    const int f   = blockIdx.y;
    const int b0  = blockIdx.x * 128;
    const int tid = threadIdx.x;
    const int wid = tid >> 5;
    const int lane = tid & 31;
    const int tq = lane >> 2, tr = lane & 3;
    const int wm = wid >> 2,  wn = wid & 3;
    const int lq = lane & 7,  quad = lane >> 3;
    const uint32_t xorv = (uint32_t)lq << 4;

    const __half* wh1g = g_wh1 + ((size_t)f << 9) * D_;
    const __half* wh2g = g_wh2 + ((size_t)f << 9) * D_;
    const float Wf = g_wmax[f];

    // ---- prologue: cp.async chunk 0 (codes 0..63, limb1 only) ----
    {
#pragma unroll
        for (int t = 0; t < 2; ++t) {
            int i = tid + t * 256;
            int n  = i >> 3;
            int ch = i & 7;
            uint32_t dst = sb + OFF_WS + (uint32_t)n * 128
                         + (((uint32_t)ch * 16) ^ ((uint32_t)(n & 7) << 4));
            CP_ASYNC16(dst, wh1g + (size_t)n * 64 + ch * 8);
        }
        CP_COMMIT();
    }

    wns[tid]       = g_wn[(f << 9) + tid];
    wns[tid + 256] = g_wn[(f << 9) + tid + 256];
    if (tid < 128) { marg[tid] = 0.f; rbk[tid] = 0u; }
#pragma unroll
    for (int t = 0; t < 8; ++t) mask[tid + t * 256] = 0u;
    __syncthreads();

    // ---- x tile -> fp16 limbs (swizzled) + per-row sumsq ----
    const float* xg = x + ((size_t)f * B_ + b0) * D_;
#pragma unroll
    for (int t = 0; t < 8; ++t) {
        int i = tid + t * 256;
        int r = i >> 4, c4 = i & 15;
        float4 v = ((const float4*)(xg + (size_t)r * D_))[c4];
        __half h1[4], h2[4];
        float vv[4] = {v.x, v.y, v.z, v.w};
#pragma unroll
        for (int j = 0; j < 4; ++j) {
            h1[j] = __float2half_rn(vv[j]);
            h2[j] = __float2half_rn(vv[j] - __half2float(h1[j]));
        }
        atomicAdd(&marg[r], vv[0]*vv[0] + vv[1]*vv[1] + vv[2]*vv[2] + vv[3]*vv[3]);
        uint32_t off = (uint32_t)r * 128
                     + (((uint32_t)c4 * 8) ^ ((uint32_t)(r & 7) << 4));
        *(uint2*)(smem + OFF_X1 + off) =
            make_uint2(pack_h2(h1[0], h1[1]), pack_h2(h1[2], h1[3]));
        *(uint2*)(smem + OFF_X2 + off) =
            make_uint2(pack_h2(h2[0], h2[1]), pack_h2(h2[2], h2[3]));
    }
    __syncthreads();
    if (tid < 128)   // threshold margin >= 2m (rigorous superset)
        marg[tid] = 2.06e-3f * sqrtf(marg[tid]) * Wf + 2e-4f;
    __syncthreads();

    const uint32_t aBase = sb + OFF_X1
        + (uint32_t)(wm * 64 + lq + ((quad & 1) << 3)) * 128;
    const uint32_t aColBase = (uint32_t)((quad >> 1) << 4);
    const uint32_t bRowOff = (uint32_t)(wn * 16 + lq) * 128;
    const uint32_t bColBase = (uint32_t)quad * 16;

    for (int c = 0; c < 8; ++c) {
        CP_WAIT0();
        __syncthreads();

        if (c < 7) {
            int cn = c + 1;
            uint32_t bufoff = (uint32_t)(cn & 1) * 8192;
#pragma unroll
            for (int t = 0; t < 2; ++t) {
                int i = tid + t * 256;
                int n  = i >> 3;
                int ch = i & 7;
                uint32_t dst = sb + OFF_WS + bufoff + (uint32_t)n * 128
                             + (((uint32_t)ch * 16) ^ ((uint32_t)(n & 7) << 4));
                CP_ASYNC16(dst, wh1g + ((size_t)(cn * 64 + n)) * 64 + ch * 8);
            }
            CP_COMMIT();
        }

        const uint32_t wsb = sb + OFF_WS + (uint32_t)(c & 1) * 8192;

        float acc[4][2][4];
#pragma unroll
        for (int i = 0; i < 4; ++i)
#pragma unroll
            for (int j = 0; j < 2; ++j)
#pragma unroll
                for (int q = 0; q < 4; ++q) acc[i][j][q] = 0.f;

#pragma unroll
        for (int kkp = 0; kkp < 2; ++kkp) {
            uint32_t bb1[2][4];
#pragma unroll
            for (int j = 0; j < 2; ++j) {
                uint32_t ba = wsb + bRowOff + (uint32_t)j * 1024
                            + ((bColBase + (uint32_t)kkp * 64) ^ xorv);
                LDSM_X4(bb1[j], ba);
            }
#pragma unroll
            for (int kk2 = 0; kk2 < 2; ++kk2) {
                const int kreg = kk2 * 2;
                const uint32_t kcol = (uint32_t)(kkp * 2 + kk2) * 32;
#pragma unroll
                for (int i = 0; i < 4; ++i) {
                    uint32_t aa = aBase + (uint32_t)i * 2048
                                + ((aColBase + kcol) ^ xorv);
                    uint32_t a1[4];
                    LDSM_X4(a1, aa);
#pragma unroll
                    for (int j = 0; j < 2; ++j)
                        mma_f16(acc[i][j], a1, bb1[j] + kreg);   // h1*w1 only
                }
            }
        }

        // fold A: per-thread local max per row-slot -> one atomicMax each
#pragma unroll
        for (int i = 0; i < 4; ++i)
#pragma unroll
            for (int h = 0; h < 2; ++h) {
                float lm = -1e30f;
#pragma unroll
                for (int j = 0; j < 2; ++j)
#pragma unroll
                    for (int c01 = 0; c01 < 2; ++c01) {
                        float s = acc[i][j][h * 2 + c01]
                                - wns[c * 64 + wn * 16 + j * 8 + tr * 2 + c01];
                        lm = fmaxf(lm, s);
                    }
                int row = wm * 64 + i * 16 + h * 8 + tq;
                atomicMax(&rbk[row], fkey(lm));
            }
        __syncthreads();

        // fold B: set candidate bits (no cap -> unconditionally correct)
#pragma unroll
        for (int i = 0; i < 4; ++i)
#pragma unroll
            for (int h = 0; h < 2; ++h) {
                int row = wm * 64 + i * 16 + h * 8 + tq;
                float thr = funkey(rbk[row]) - marg[row];
#pragma unroll
                for (int j = 0; j < 2; ++j)
#pragma unroll
                    for (int c01 = 0; c01 < 2; ++c01) {
                        int kg = c * 64 + wn * 16 + j * 8 + tr * 2 + c01;
                        float s = acc[i][j][h * 2 + c01] - wns[kg];
                        if (s >= thr)
                            atomicOr(&mask[row * 16 + (kg >> 5)],
                                     1u << (kg & 31));
                    }
            }
    }
    __syncthreads();

    // ---- stage 2: parallel exact fp32 rescore (2 threads per row) ----
    {
        const int row  = tid >> 1;
        const int half = tid & 1;
        const uint32_t xorr = (uint32_t)(row & 7) << 4;
        float bs = -1e30f;
        int bk = 0x7FFFFFFF;
#pragma unroll 1
        for (int w8 = 0; w8 < 8; ++w8) {
            int wd = half * 8 + w8;
            uint32_t m = mask[row * 16 + wd];
            while (m) {
                int b = __ffs(m) - 1;
                m &= m - 1;
                int k = wd * 32 + b;
                float s = 0.f;
                const __half2* w1p = (const __half2*)(wh1g + (size_t)k * 64);
                const __half2* w2p = (const __half2*)(wh2g + (size_t)k * 64);
#pragma unroll 8
                for (int d2 = 0; d2 < 32; ++d2) {
                    uint32_t off = (uint32_t)row * 128
                                 + (((uint32_t)d2 * 4) ^ xorr);
                    float2 x1 = __half22float2(*(__half2*)(smem + OFF_X1 + off));
                    float2 x2 = __half22float2(*(__half2*)(smem + OFF_X2 + off));
                    float2 w1 = __half22float2(w1p[d2]);
                    float2 w2 = __half22float2(w2p[d2]);
                    s += (x1.x + x2.x) * (w1.x + w2.x)
                       + (x1.y + x2.y) * (w1.y + w2.y);
                }
                s -= wns[k];
                if (s > bs || (s == bs && k < bk)) { bs = s; bk = k; }
            }
        }
        bs2[tid] = bs;
        bk2[tid] = bk;
    }
    __syncthreads();

    if (tid < 128) {
        float s0 = bs2[2 * tid], s1 = bs2[2 * tid + 1];
        int   k0 = bk2[2 * tid], k1 = bk2[2 * tid + 1];
        sidx[tid] = (s0 > s1 || (s0 == s1 && k0 < k1)) ? k0 : k1;
    }
    __syncthreads();

    // ---- gather (q = h1 + h2) + loss ----
    float lsum = 0.f;
    float* og = out + ((size_t)f * B_ + b0) * D_;
    for (int e = tid; e < 128 * D_; e += NTHREADS) {
        int r = e >> 6, d = e & 63;
        size_t gi = (size_t)sidx[r] * D_ + d;
        float q  = __half2float(wh1g[gi]) + __half2float(wh2g[gi]);
        float xv = xg[e];
        og[e] = q;
        float dif = q - xv;
        lsum += dif * dif;
    }
#pragma unroll
    for (int o = 16; o > 0; o >>= 1)
        lsum += __shfl_xor_sync(0xFFFFFFFFu, lsum, o);
    if ((tid & 31) == 0) red8[wid] = lsum;
    __syncthreads();

    __shared__ int s_last;
    if (tid == 0) {
        float t = 0.f;
#pragma unroll
        for (int i = 0; i < 8; ++i) t += red8[i];
        g_partial[blockIdx.y * gridDim.x + blockIdx.x] = t;
        __threadfence();
        int old = atomicAdd(&g_count, 1);
        s_last = (old == 1023) ? 1 : 0;
    }
    __syncthreads();

    if (s_last) {
        float s = 0.f;
#pragma unroll
        for (int t = 0; t < 4; ++t) s += g_partial[tid + t * 256];
#pragma unroll
        for (int o = 16; o > 0; o >>= 1)
            s += __shfl_xor_sync(0xFFFFFFFFu, s, o);
        if ((tid & 31) == 0) red8[wid] = s;
        __syncthreads();
        if (tid == 0) {
            float t = 0.f;
#pragma unroll
            for (int i = 0; i < 8; ++i) t += red8[i];
            out[loss_pos] = t * (1.25f / (float)(F_ * B_ * D_));
            g_count = 0;
        }
    }
}

// ---------------------------------------------------------------------------
extern "C" void kernel_launch(void* const* d_in, const int* in_sizes, int n_in,
                              void* d_out, int out_size) {
    const float* x = (const float*)d_in[0];   // (F,B,D)
    const float* w = (const float*)d_in[1];   // (F,D,K)
    float* out = (float*)d_out;

    cudaFuncSetAttribute(vq_main, cudaFuncAttributeMaxDynamicSharedMemorySize,
                         SMEM_BYTES);

    dim3 pgrid(16, 32);
    vq_prep<<<pgrid, 256>>>(w);

    dim3 grid(B_ / 128, F_);
    vq_main<<<grid, NTHREADS, SMEM_BYTES>>>(x, out, out_size - 1);
}

// round 14
// speedup vs baseline: 1.1888x; 1.1134x over previous
#include <cuda_runtime.h>
#include <cuda_fp16.h>
#include <cstdint>

#define F_ 32
#define B_ 4096
#define D_ 64
#define K_ 512
#define NTHREADS 256
#define ROWS 64
#define SCSTR 1052          // score row stride bytes (526 halves, gcd trick)

// ---------------- device scratch ----------------
__device__ __half g_wh1[(size_t)F_ * K_ * D_];  // fp16 limb1, [f][k][d]
__device__ __half g_wh2[(size_t)F_ * K_ * D_];  // fp16 limb2, [f][k][d]
__device__ float  g_wn [F_ * K_];               // 0.5*||w_k||^2
__device__ float  g_wmax[F_];                   // max_k ||w_k||
__device__ float  g_partial[2048];
__device__ int    g_count;

__device__ __forceinline__ uint32_t smem_u32(const void* p) {
    uint32_t a;
    asm("{ .reg .u64 t; cvta.to.shared.u64 t, %1; cvt.u32.u64 %0, t; }"
        : "=r"(a) : "l"(p));
    return a;
}

#define LDSM_X4(r_, addr_) \
    asm volatile("ldmatrix.sync.aligned.m8n8.x4.shared.b16 {%0,%1,%2,%3}, [%4];" \
        : "=r"((r_)[0]), "=r"((r_)[1]), "=r"((r_)[2]), "=r"((r_)[3]) : "r"(addr_))

#define CP_ASYNC16(dst_, src_) \
    asm volatile("cp.async.cg.shared.global [%0], [%1], 16;" :: "r"(dst_), "l"(src_))
#define CP_COMMIT() asm volatile("cp.async.commit_group;" ::: "memory")
#define CP_WAIT0()  asm volatile("cp.async.wait_group 0;" ::: "memory")

__device__ __forceinline__ void mma_f16(float* c, const uint32_t* a,
                                        const uint32_t* b) {
    asm volatile(
        "mma.sync.aligned.m16n8k16.row.col.f32.f16.f16.f32 "
        "{%0,%1,%2,%3}, {%4,%5,%6,%7}, {%8,%9}, {%0,%1,%2,%3};"
        : "+f"(c[0]), "+f"(c[1]), "+f"(c[2]), "+f"(c[3])
        : "r"(a[0]), "r"(a[1]), "r"(a[2]), "r"(a[3]), "r"(b[0]), "r"(b[1]));
}

__device__ __forceinline__ uint32_t pack_h2(__half a, __half b) {
    __half2 h = __halves2half2(a, b);
    return *(uint32_t*)&h;
}

// order-preserving float <-> uint key
__device__ __forceinline__ uint32_t fkey(float v) {
    int i = __float_as_int(v);
    return (i >= 0) ? ((uint32_t)i | 0x80000000u) : (uint32_t)(~i);
}
__device__ __forceinline__ float funkey(uint32_t k) {
    int i = (k & 0x80000000u) ? (int)(k & 0x7FFFFFFFu) : ~(int)k;
    return __int_as_float(i);
}

// smem layout (bytes); x/ws tiles: 128B rows + SW128 XOR swizzle
#define OFF_WNS   0        // 512 f32 (2048)
#define OFF_RBK   2048     // 64 uint (256)
#define OFF_MG    2304     // 64 f32 (256)
#define OFF_SIDX  2560     // 64 int (256)
#define OFF_RED8  2816     // 8 f32 (32)
#define OFF_BS2   2848     // 256 f32 (1024)
#define OFF_BK2   3872     // 256 int (1024)
#define OFF_MASK  4896     // 64 x 16 uint (4096)
#define OFF_X1    9088     // x limb1, 64x128B (8192), 128-aligned
#define OFF_X2    17280    // x limb2 (8192)
#define OFF_SC    25472    // scores fp16, 64 x SCSTR (67328)
#define OFF_WS    92800    // ws limb1, 2 bufs x 8192 (16384)
#define SMEM_BYTES 109184

// ---------------------------------------------------------------------------
// Prep: transpose + fp16 2-limb split + norms + per-f max norm.
// ---------------------------------------------------------------------------
__global__ void vq_prep(const float* __restrict__ w) {
    __shared__ float ts[32][65];
    __shared__ float ps[32][9];
    const int f = blockIdx.y, kt = blockIdx.x, tid = threadIdx.x;
    const float* wf = w + (size_t)f * D_ * K_ + kt * 32;

    for (int i = tid; i < 64 * 32; i += 256) {
        int d = i >> 5, kk = i & 31;
        ts[kk][d] = wf[(size_t)d * K_ + kk];
    }
    __syncthreads();

    size_t base = ((size_t)f * K_ + (size_t)kt * 32) * D_;
    for (int i = tid; i < 32 * 64; i += 256) {
        int kk = i >> 6, d = i & 63;
        float v = ts[kk][d];
        __half h1 = __float2half_rn(v);
        __half h2 = __float2half_rn(v - __half2float(h1));
        g_wh1[base + i] = h1;
        g_wh2[base + i] = h2;
    }
    {
        int kk = tid >> 3, seg = tid & 7;
        float s = 0.f;
#pragma unroll
        for (int d8 = 0; d8 < 8; ++d8) {
            float v = ts[kk][seg * 8 + d8];
            s += v * v;
        }
        ps[kk][seg] = s;
    }
    __syncthreads();
    if (tid < 32) {
        float s = 0.f;
#pragma unroll
        for (int g = 0; g < 8; ++g) s += ps[tid][g];
        g_wn[f * K_ + kt * 32 + tid] = 0.5f * s;
        atomicMax((int*)&g_wmax[f], __float_as_int(sqrtf(s)));
    }
}

// ---------------------------------------------------------------------------
// Main: stage1 = h1*w1 approx GEMM -> ALL scores in smem (fp16);
// exact global row max -> margin candidates (bitmask) -> fp32 rescore.
// grid (64, 32): 64 rows per block. 8 warps (2M x 4N), warp tile 32x16.
// ---------------------------------------------------------------------------
__global__ __launch_bounds__(NTHREADS)
void vq_main(const float* __restrict__ x, float* __restrict__ out,
             int loss_pos) {
    extern __shared__ __align__(1024) char smem[];
    const uint32_t sb = smem_u32(smem);
    float*    wns  = (float*)(smem + OFF_WNS);
    uint32_t* rbk  = (uint32_t*)(smem + OFF_RBK);
    float*    marg = (float*)(smem + OFF_MG);
    int*      sidx = (int*)(smem + OFF_SIDX);
    float*    red8 = (float*)(smem + OFF_RED8);
    float*    bs2  = (float*)(smem + OFF_BS2);
    int*      bk2  = (int*)(smem + OFF_BK2);
    uint32_t* mask = (uint32_t*)(smem + OFF_MASK);

    const int f   = blockIdx.y;
    const int b0  = blockIdx.x * ROWS;
    const int tid = threadIdx.x;
    const int wid = tid >> 5;
    const int lane = tid & 31;
    const int tq = lane >> 2, tr = lane & 3;
    const int wm = wid >> 2,  wn = wid & 3;
    const int lq = lane & 7,  quad = lane >> 3;
    const uint32_t xorv = (uint32_t)lq << 4;

    const __half* wh1g = g_wh1 + ((size_t)f << 9) * D_;
    const __half* wh2g = g_wh2 + ((size_t)f << 9) * D_;
    const float Wf = g_wmax[f];

    // ---- prologue: cp.async chunk 0 (codes 0..63, limb1) ----
    {
#pragma unroll
        for (int t = 0; t < 2; ++t) {
            int i = tid + t * 256;
            int n  = i >> 3;
            int ch = i & 7;
            uint32_t dst = sb + OFF_WS + (uint32_t)n * 128
                         + (((uint32_t)ch * 16) ^ ((uint32_t)(n & 7) << 4));
            CP_ASYNC16(dst, wh1g + (size_t)n * 64 + ch * 8);
        }
        CP_COMMIT();
    }

    wns[tid]       = g_wn[(f << 9) + tid];
    wns[tid + 256] = g_wn[(f << 9) + tid + 256];
    if (tid < ROWS) { marg[tid] = 0.f; rbk[tid] = 0u; }
#pragma unroll
    for (int t = 0; t < 4; ++t) mask[tid + t * 256] = 0u;
    __syncthreads();

    // ---- x tile (64 rows) -> fp16 limbs (swizzled) + per-row sumsq ----
    const float* xg = x + ((size_t)f * B_ + b0) * D_;
#pragma unroll
    for (int t = 0; t < 4; ++t) {
        int i = tid + t * 256;                 // [0,1024)
        int r = i >> 4, c4 = i & 15;
        float4 v = ((const float4*)(xg + (size_t)r * D_))[c4];
        __half h1[4], h2[4];
        float vv[4] = {v.x, v.y, v.z, v.w};
#pragma unroll
        for (int j = 0; j < 4; ++j) {
            h1[j] = __float2half_rn(vv[j]);
            h2[j] = __float2half_rn(vv[j] - __half2float(h1[j]));
        }
        atomicAdd(&marg[r], vv[0]*vv[0] + vv[1]*vv[1] + vv[2]*vv[2] + vv[3]*vv[3]);
        uint32_t off = (uint32_t)r * 128
                     + (((uint32_t)c4 * 8) ^ ((uint32_t)(r & 7) << 4));
        *(uint2*)(smem + OFF_X1 + off) =
            make_uint2(pack_h2(h1[0], h1[1]), pack_h2(h1[2], h1[3]));
        *(uint2*)(smem + OFF_X2 + off) =
            make_uint2(pack_h2(h2[0], h2[1]), pack_h2(h2[2], h2[3]));
    }
    __syncthreads();
    if (tid < ROWS)   // >= 2m (approx err) + fp16 score-storage err + slack
        marg[tid] = 2.06e-3f * sqrtf(marg[tid]) * Wf + 4.5e-3f;
    __syncthreads();

    const uint32_t aBase = sb + OFF_X1
        + (uint32_t)(wm * 32 + lq + ((quad & 1) << 3)) * 128;
    const uint32_t aColBase = (uint32_t)((quad >> 1) << 4);
    const uint32_t bRowOff = (uint32_t)(wn * 16 + lq) * 128;
    const uint32_t bColBase = (uint32_t)quad * 16;

    // ---- stage 1: h1*w1 GEMM, scores -> smem fp16 ----
    for (int c = 0; c < 8; ++c) {
        CP_WAIT0();
        __syncthreads();

        if (c < 7) {
            int cn = c + 1;
            uint32_t bufoff = (uint32_t)(cn & 1) * 8192;
#pragma unroll
            for (int t = 0; t < 2; ++t) {
                int i = tid + t * 256;
                int n  = i >> 3;
                int ch = i & 7;
                uint32_t dst = sb + OFF_WS + bufoff + (uint32_t)n * 128
                             + (((uint32_t)ch * 16) ^ ((uint32_t)(n & 7) << 4));
                CP_ASYNC16(dst, wh1g + ((size_t)(cn * 64 + n)) * 64 + ch * 8);
            }
            CP_COMMIT();
        }

        const uint32_t wsb = sb + OFF_WS + (uint32_t)(c & 1) * 8192;

        float acc[2][2][4];
#pragma unroll
        for (int i = 0; i < 2; ++i)
#pragma unroll
            for (int j = 0; j < 2; ++j)
#pragma unroll
                for (int q = 0; q < 4; ++q) acc[i][j][q] = 0.f;

#pragma unroll
        for (int kkp = 0; kkp < 2; ++kkp) {
            uint32_t bb1[2][4];
#pragma unroll
            for (int j = 0; j < 2; ++j) {
                uint32_t ba = wsb + bRowOff + (uint32_t)j * 1024
                            + ((bColBase + (uint32_t)kkp * 64) ^ xorv);
                LDSM_X4(bb1[j], ba);
            }
#pragma unroll
            for (int kk2 = 0; kk2 < 2; ++kk2) {
                const int kreg = kk2 * 2;
                const uint32_t kcol = (uint32_t)(kkp * 2 + kk2) * 32;
#pragma unroll
                for (int i = 0; i < 2; ++i) {
                    uint32_t aa = aBase + (uint32_t)i * 2048
                                + ((aColBase + kcol) ^ xorv);
                    uint32_t a1[4];
                    LDSM_X4(a1, aa);
#pragma unroll
                    for (int j = 0; j < 2; ++j)
                        mma_f16(acc[i][j], a1, bb1[j] + kreg);
                }
            }
        }

        // store scores - norms as fp16 (conflict-free: banks 7*tq + tr)
#pragma unroll
        for (int i = 0; i < 2; ++i)
#pragma unroll
            for (int h = 0; h < 2; ++h) {
                int row = wm * 32 + i * 16 + h * 8 + tq;
                char* rp = smem + OFF_SC + row * SCSTR;
#pragma unroll
                for (int j = 0; j < 2; ++j) {
                    int k = c * 64 + wn * 16 + j * 8 + tr * 2;
                    float s0 = acc[i][j][h * 2 + 0] - wns[k];
                    float s1 = acc[i][j][h * 2 + 1] - wns[k + 1];
                    *(__half2*)(rp + k * 2) = __floats2half2_rn(s0, s1);
                }
            }
    }
    __syncthreads();

    // ---- scan 1: exact global row max ----
    {
        int row = tid & 63, seg = tid >> 6;
        const char* sp = smem + OFF_SC + row * SCSTR + seg * 256;
        float m = -1e30f;
#pragma unroll 8
        for (int it = 0; it < 64; ++it) {
            float2 v = __half22float2(*(const __half2*)(sp + it * 4));
            m = fmaxf(m, fmaxf(v.x, v.y));
        }
        atomicMax(&rbk[row], fkey(m));
    }
    __syncthreads();

    // ---- scan 2: candidates vs true max ----
    {
        int row = tid & 63, seg = tid >> 6;
        const char* sp = smem + OFF_SC + row * SCSTR + seg * 256;
        float thr = funkey(rbk[row]) - marg[row];
#pragma unroll 8
        for (int it = 0; it < 64; ++it) {
            float2 v = __half22float2(*(const __half2*)(sp + it * 4));
            int k = seg * 128 + it * 2;
            if (v.x >= thr) atomicOr(&mask[row * 16 + (k >> 5)], 1u << (k & 31));
            if (v.y >= thr) atomicOr(&mask[row * 16 + ((k+1) >> 5)], 1u << ((k+1) & 31));
        }
    }
    __syncthreads();

    // ---- stage 2: exact fp32 rescore (4 threads per row) ----
    {
        const int row = tid & 63, seg = tid >> 6;
        const uint32_t xorr = (uint32_t)(row & 7) << 4;
        float bs = -1e30f;
        int bk = 0x7FFFFFFF;
#pragma unroll 1
        for (int w8 = 0; w8 < 4; ++w8) {
            int wd = seg * 4 + w8;
            uint32_t m = mask[row * 16 + wd];
            while (m) {
                int b = __ffs(m) - 1;
                m &= m - 1;
                int k = wd * 32 + b;
                float s = 0.f;
                const __half2* w1p = (const __half2*)(wh1g + (size_t)k * 64);
                const __half2* w2p = (const __half2*)(wh2g + (size_t)k * 64);
#pragma unroll 8
                for (int d2 = 0; d2 < 32; ++d2) {
                    uint32_t off = (uint32_t)row * 128
                                 + (((uint32_t)d2 * 4) ^ xorr);
                    float2 x1 = __half22float2(*(__half2*)(smem + OFF_X1 + off));
                    float2 x2 = __half22float2(*(__half2*)(smem + OFF_X2 + off));
                    float2 w1 = __half22float2(w1p[d2]);
                    float2 w2 = __half22float2(w2p[d2]);
                    s += (x1.x + x2.x) * (w1.x + w2.x)
                       + (x1.y + x2.y) * (w1.y + w2.y);
                }
                s -= wns[k];
                if (s > bs || (s == bs && k < bk)) { bs = s; bk = k; }
            }
        }
        bs2[tid] = bs;
        bk2[tid] = bk;
    }
    __syncthreads();

    if (tid < ROWS) {
        float bsf = -1e30f;
        int bkf = 0x7FFFFFFF;
#pragma unroll
        for (int s = 0; s < 4; ++s) {       // seg ascending == k ascending
            float v = bs2[tid + 64 * s];
            int  kk = bk2[tid + 64 * s];
            if (v > bsf || (v == bsf && kk < bkf)) { bsf = v; bkf = kk; }
        }
        sidx[tid] = bkf;
    }
    __syncthreads();

    // ---- gather (q = h1 + h2) + loss ----
    float lsum = 0.f;
    float* og = out + ((size_t)f * B_ + b0) * D_;
    for (int e = tid; e < ROWS * D_; e += NTHREADS) {
        int r = e >> 6, d = e & 63;
        size_t gi = (size_t)sidx[r] * D_ + d;
        float q  = __half2float(wh1g[gi]) + __half2float(wh2g[gi]);
        float xv = xg[e];
        og[e] = q;
        float dif = q - xv;
        lsum += dif * dif;
    }
#pragma unroll
    for (int o = 16; o > 0; o >>= 1)
        lsum += __shfl_xor_sync(0xFFFFFFFFu, lsum, o);
    if ((tid & 31) == 0) red8[wid] = lsum;
    __syncthreads();

    __shared__ int s_last;
    if (tid == 0) {
        float t = 0.f;
#pragma unroll
        for (int i = 0; i < 8; ++i) t += red8[i];
        g_partial[blockIdx.y * gridDim.x + blockIdx.x] = t;
        __threadfence();
        int old = atomicAdd(&g_count, 1);
        s_last = (old == 2047) ? 1 : 0;
    }
    __syncthreads();

    if (s_last) {
        float s = 0.f;
#pragma unroll
        for (int t = 0; t < 8; ++t) s += g_partial[tid + t * 256];
#pragma unroll
        for (int o = 16; o > 0; o >>= 1)
            s += __shfl_xor_sync(0xFFFFFFFFu, s, o);
        if ((tid & 31) == 0) red8[wid] = s;
        __syncthreads();
        if (tid == 0) {
            float t = 0.f;
#pragma unroll
            for (int i = 0; i < 8; ++i) t += red8[i];
            out[loss_pos] = t * (1.25f / (float)(F_ * B_ * D_));
            g_count = 0;
        }
    }
}

// ---------------------------------------------------------------------------
extern "C" void kernel_launch(void* const* d_in, const int* in_sizes, int n_in,
                              void* d_out, int out_size) {
    const float* x = (const float*)d_in[0];   // (F,B,D)
    const float* w = (const float*)d_in[1];   // (F,D,K)
    float* out = (float*)d_out;

    cudaFuncSetAttribute(vq_main, cudaFuncAttributeMaxDynamicSharedMemorySize,
                         SMEM_BYTES);

    dim3 pgrid(16, 32);
    vq_prep<<<pgrid, 256>>>(w);

    dim3 grid(B_ / ROWS, F_);
    vq_main<<<grid, NTHREADS, SMEM_BYTES>>>(x, out, out_size - 1);
}

// round 15
// speedup vs baseline: 2.8071x; 2.3614x over previous
#include <cuda_runtime.h>
#include <cuda_fp16.h>
#include <cstdint>

#define F_ 32
#define B_ 4096
#define D_ 64
#define K_ 512
#define NTHREADS 256
#define NTILES 1024
#define NCTAS 456

// ---------------- device scratch ----------------
__device__ __half g_wh1[(size_t)F_ * K_ * D_];  // fp16 limb1, [f][k][d]
__device__ __half g_wh2[(size_t)F_ * K_ * D_];  // fp16 limb2, [f][k][d]
__device__ float  g_wn [F_ * K_];               // 0.5*||w_k||^2
__device__ float  g_partial[NTILES];            // per-TILE loss partials
__device__ int    g_count;
__device__ int    g_tile;

__device__ __forceinline__ uint32_t smem_u32(const void* p) {
    uint32_t a;
    asm("{ .reg .u64 t; cvta.to.shared.u64 t, %1; cvt.u32.u64 %0, t; }"
        : "=r"(a) : "l"(p));
    return a;
}

#define LDSM_X4(r_, addr_) \
    asm volatile("ldmatrix.sync.aligned.m8n8.x4.shared.b16 {%0,%1,%2,%3}, [%4];" \
        : "=r"((r_)[0]), "=r"((r_)[1]), "=r"((r_)[2]), "=r"((r_)[3]) : "r"(addr_))

#define CP_ASYNC16(dst_, src_) \
    asm volatile("cp.async.cg.shared.global [%0], [%1], 16;" :: "r"(dst_), "l"(src_))
#define CP_COMMIT() asm volatile("cp.async.commit_group;" ::: "memory")
#define CP_WAIT0()  asm volatile("cp.async.wait_group 0;" ::: "memory")

__device__ __forceinline__ void mma_f16(float* c, const uint32_t* a,
                                        const uint32_t* b) {
    asm volatile(
        "mma.sync.aligned.m16n8k16.row.col.f32.f16.f16.f32 "
        "{%0,%1,%2,%3}, {%4,%5,%6,%7}, {%8,%9}, {%0,%1,%2,%3};"
        : "+f"(c[0]), "+f"(c[1]), "+f"(c[2]), "+f"(c[3])
        : "r"(a[0]), "r"(a[1]), "r"(a[2]), "r"(a[3]), "r"(b[0]), "r"(b[1]));
}

__device__ __forceinline__ uint32_t pack_h2(__half a, __half b) {
    __half2 h = __halves2half2(a, b);
    return *(uint32_t*)&h;
}

// smem (bytes). 128B rows + SW128 XOR swizzle: phys = row*128 + (col ^ ((row&7)<<4))
#define OFF_WNS  0
#define OFF_SIDX 2048
#define OFF_RED8 2560
#define OFF_TILE 2592      // s_t broadcast
#define OFF_X1   4096
#define OFF_X2   20480
#define OFF_WS   36864
#define SMEM_BYTES 69632

// ---------------------------------------------------------------------------
// Prep: transpose + fp16 2-limb split + norms. grid (16, 32) x 256.
// ---------------------------------------------------------------------------
__global__ void vq_prep(const float* __restrict__ w) {
    __shared__ float ts[32][65];
    __shared__ float ps[32][9];
    const int f = blockIdx.y, kt = blockIdx.x, tid = threadIdx.x;
    const float* wf = w + (size_t)f * D_ * K_ + kt * 32;

    for (int i = tid; i < 64 * 32; i += 256) {
        int d = i >> 5, kk = i & 31;
        ts[kk][d] = wf[(size_t)d * K_ + kk];
    }
    __syncthreads();

    size_t base = ((size_t)f * K_ + (size_t)kt * 32) * D_;
    for (int i = tid; i < 32 * 64; i += 256) {
        int kk = i >> 6, d = i & 63;
        float v = ts[kk][d];
        __half h1 = __float2half_rn(v);
        __half h2 = __float2half_rn(v - __half2float(h1));
        g_wh1[base + i] = h1;
        g_wh2[base + i] = h2;
    }
    {
        int kk = tid >> 3, seg = tid & 7;
        float s = 0.f;
#pragma unroll
        for (int d8 = 0; d8 < 8; ++d8) {
            float v = ts[kk][seg * 8 + d8];
            s += v * v;
        }
        ps[kk][seg] = s;
    }
    __syncthreads();
    if (tid < 32) {
        float s = 0.f;
#pragma unroll
        for (int g = 0; g < 8; ++g) s += ps[tid][g];
        g_wn[f * K_ + kt * 32 + tid] = 0.5f * s;
    }
}

// ---------------------------------------------------------------------------
// Main: PERSISTENT CTAs (456) stealing 128-row tiles; per tile: fp16
// 3-product mma.sync GEMM (R8 inner loop), cp.async double-buffered B,
// fused argmax+gather+loss. Tile-indexed partials -> deterministic loss.
// ---------------------------------------------------------------------------
__global__ __launch_bounds__(NTHREADS, 3)
void vq_main(const float* __restrict__ x, float* __restrict__ out,
             int loss_pos) {
    extern __shared__ __align__(1024) char smem[];
    const uint32_t sb = smem_u32(smem);
    float* wns  = (float*)(smem + OFF_WNS);
    int*   sidx = (int*)(smem + OFF_SIDX);
    float* red8 = (float*)(smem + OFF_RED8);
    int*   s_t  = (int*)(smem + OFF_TILE);
    float* red_v = (float*)(smem + OFF_WS);
    int*   red_i = (int*)(smem + OFF_WS + 8192);

    const int tid = threadIdx.x;
    const int wid = tid >> 5;
    const int lane = tid & 31;
    const int tq = lane >> 2, tr = lane & 3;
    const int wm = wid >> 2,  wn = wid & 3;
    const int lq = lane & 7,  quad = lane >> 3;
    const uint32_t xorv = (uint32_t)lq << 4;

    for (;;) {
        __syncthreads();    // fence prior epilogue smem reads & s_t reuse
        if (tid == 0) *s_t = atomicAdd(&g_tile, 1);
        __syncthreads();
        const int t = *s_t;
        if (t >= NTILES) break;

        const int f  = t >> 5;
        const int b0 = (t & 31) * 128;
        const __half* wh1g = g_wh1 + ((size_t)f << 9) * D_;
        const __half* wh2g = g_wh2 + ((size_t)f << 9) * D_;

        // ---- prefetch chunk 0 (codes 0..63, both limbs) into buf 0 ----
#pragma unroll
        for (int tt = 0; tt < 4; ++tt) {
            int i = tid + tt * 256;             // [0,1024)
            int limb = i >> 9;
            int n    = (i >> 3) & 63;
            int ch   = i & 7;
            uint32_t dst = sb + OFF_WS + (uint32_t)limb * 8192
                         + (uint32_t)n * 128
                         + (((uint32_t)ch * 16) ^ ((uint32_t)(n & 7) << 4));
            const __half* src = (limb ? wh2g : wh1g) + (size_t)n * 64 + ch * 8;
            CP_ASYNC16(dst, src);
        }
        CP_COMMIT();

        wns[tid]       = g_wn[(f << 9) + tid];
        wns[tid + 256] = g_wn[(f << 9) + tid + 256];

        // ---- x tile -> fp16 limbs, swizzled 128B rows ----
        const float* xg = x + ((size_t)f * B_ + b0) * D_;
#pragma unroll
        for (int tt = 0; tt < 8; ++tt) {
            int i = tid + tt * 256;             // [0,2048)
            int r = i >> 4, c4 = i & 15;
            float4 v = ((const float4*)(xg + (size_t)r * D_))[c4];
            __half h1[4], h2[4];
            float vv[4] = {v.x, v.y, v.z, v.w};
#pragma unroll
            for (int j = 0; j < 4; ++j) {
                h1[j] = __float2half_rn(vv[j]);
                h2[j] = __float2half_rn(vv[j] - __half2float(h1[j]));
            }
            uint32_t off = (uint32_t)r * 128
                         + (((uint32_t)c4 * 8) ^ ((uint32_t)(r & 7) << 4));
            *(uint2*)(smem + OFF_X1 + off) =
                make_uint2(pack_h2(h1[0], h1[1]), pack_h2(h1[2], h1[3]));
            *(uint2*)(smem + OFF_X2 + off) =
                make_uint2(pack_h2(h2[0], h2[1]), pack_h2(h2[2], h2[3]));
        }

        float best[8];
        int   bidx[8];
#pragma unroll
        for (int i = 0; i < 8; ++i) { best[i] = -1e30f; bidx[i] = 0; }

        const uint32_t aBase = sb + OFF_X1
            + (uint32_t)(wm * 64 + lq + ((quad & 1) << 3)) * 128;
        const uint32_t aColBase = (uint32_t)((quad >> 1) << 4);
        const uint32_t bRowOff = (uint32_t)(wn * 16 + lq) * 128;
        const uint32_t bColBase = (uint32_t)quad * 16;

        for (int c = 0; c < 8; ++c) {
            CP_WAIT0();
            __syncthreads();

            if (c < 7) {
                int cn = c + 1;
                uint32_t bufoff = (uint32_t)(cn & 1) * 16384;
#pragma unroll
                for (int tt = 0; tt < 4; ++tt) {
                    int i = tid + tt * 256;
                    int limb = i >> 9;
                    int n    = (i >> 3) & 63;
                    int ch   = i & 7;
                    uint32_t dst = sb + OFF_WS + bufoff + (uint32_t)limb * 8192
                                 + (uint32_t)n * 128
                                 + (((uint32_t)ch * 16) ^ ((uint32_t)(n & 7) << 4));
                    const __half* src = (limb ? wh2g : wh1g)
                                      + ((size_t)(cn * 64 + n)) * 64 + ch * 8;
                    CP_ASYNC16(dst, src);
                }
                CP_COMMIT();
            }

            const uint32_t wsb = sb + OFF_WS + (uint32_t)(c & 1) * 16384;

            float acc[4][2][4];
#pragma unroll
            for (int i = 0; i < 4; ++i)
#pragma unroll
                for (int j = 0; j < 2; ++j)
#pragma unroll
                    for (int q = 0; q < 4; ++q) acc[i][j][q] = 0.f;

#pragma unroll
            for (int kkp = 0; kkp < 2; ++kkp) {
                uint32_t bb1[2][4], bb2[2][4];
#pragma unroll
                for (int j = 0; j < 2; ++j) {
                    uint32_t ba = wsb + bRowOff + (uint32_t)j * 1024
                                + ((bColBase + (uint32_t)kkp * 64) ^ xorv);
                    LDSM_X4(bb1[j], ba);
                    LDSM_X4(bb2[j], ba + 8192);
                }
#pragma unroll
                for (int kk2 = 0; kk2 < 2; ++kk2) {
                    const int kreg = kk2 * 2;
                    const uint32_t kcol = (uint32_t)(kkp * 2 + kk2) * 32;
                    uint32_t a1[4][4], a2[4][4];
#pragma unroll
                    for (int i = 0; i < 4; ++i) {
                        uint32_t aa = aBase + (uint32_t)i * 2048
                                    + ((aColBase + kcol) ^ xorv);
                        LDSM_X4(a1[i], aa);
                        LDSM_X4(a2[i], aa + 16384);
                    }
#pragma unroll
                    for (int i = 0; i < 4; ++i)
#pragma unroll
                        for (int j = 0; j < 2; ++j)
                            mma_f16(acc[i][j], a1[i], &bb1[j][kreg]);  // h1*w1
#pragma unroll
                    for (int i = 0; i < 4; ++i)
#pragma unroll
                        for (int j = 0; j < 2; ++j)
                            mma_f16(acc[i][j], a1[i], &bb2[j][kreg]);  // h1*w2
#pragma unroll
                    for (int i = 0; i < 4; ++i)
#pragma unroll
                        for (int j = 0; j < 2; ++j)
                            mma_f16(acc[i][j], a2[i], &bb1[j][kreg]);  // h2*w1
                }
            }

            // fold chunk scores into running argmax (k ascending; strict >)
#pragma unroll
            for (int j = 0; j < 2; ++j)
#pragma unroll
                for (int c01 = 0; c01 < 2; ++c01) {
                    int kg = c * 64 + wn * 16 + j * 8 + tr * 2 + c01;
                    float wnv = wns[kg];
#pragma unroll
                    for (int i = 0; i < 4; ++i)
#pragma unroll
                        for (int h = 0; h < 2; ++h) {
                            float s = acc[i][j][h * 2 + c01] - wnv;
                            int slot = i * 2 + h;
                            if (s > best[slot]) { best[slot] = s; bidx[slot] = kg; }
                        }
                }
        }

        __syncthreads();   // ws reads done; overlay reduction arrays

#pragma unroll
        for (int i = 0; i < 4; ++i)
#pragma unroll
            for (int h = 0; h < 2; ++h) {
                int row = wm * 64 + i * 16 + h * 8 + tq;
                red_v[row * 16 + wn * 4 + tr] = best[i * 2 + h];
                red_i[row * 16 + wn * 4 + tr] = bidx[i * 2 + h];
            }
        __syncthreads();

        if (tid < 128) {
            float bv = -1e30f;
            int bk = 0x7FFFFFFF;
#pragma unroll
            for (int t2 = 0; t2 < 16; ++t2) {
                float v = red_v[tid * 16 + t2];
                int  kk = red_i[tid * 16 + t2];
                if (v > bv || (v == bv && kk < bk)) { bv = v; bk = kk; }
            }
            sidx[tid] = bk;
        }
        __syncthreads();

        // ---- gather (q = h1 + h2) + loss ----
        float lsum = 0.f;
        float* og = out + ((size_t)f * B_ + b0) * D_;
        for (int e = tid; e < 128 * D_; e += NTHREADS) {
            int r = e >> 6, d = e & 63;
            size_t gi = (size_t)sidx[r] * D_ + d;
            float q  = __half2float(wh1g[gi]) + __half2float(wh2g[gi]);
            float xv = xg[e];
            og[e] = q;
            float dif = q - xv;
            lsum += dif * dif;
        }
#pragma unroll
        for (int o = 16; o > 0; o >>= 1)
            lsum += __shfl_xor_sync(0xFFFFFFFFu, lsum, o);
        if ((tid & 31) == 0) red8[wid] = lsum;
        __syncthreads();
        if (tid == 0) {
            float tt = 0.f;
#pragma unroll
            for (int i = 0; i < 8; ++i) tt += red8[i];
            g_partial[t] = tt;   // tile-indexed -> deterministic final sum
        }
    }

    // ---- all tiles done: last CTA reduces loss, resets counters ----
    __shared__ int s_last;
    if (tid == 0) {
        __threadfence();
        int old = atomicAdd(&g_count, 1);
        s_last = (old == NCTAS - 1) ? 1 : 0;
    }
    __syncthreads();

    if (s_last) {
        float s = 0.f;
#pragma unroll
        for (int tt = 0; tt < NTILES / NTHREADS; ++tt)
            s += g_partial[tid + tt * NTHREADS];
#pragma unroll
        for (int o = 16; o > 0; o >>= 1)
            s += __shfl_xor_sync(0xFFFFFFFFu, s, o);
        if ((tid & 31) == 0) red8[wid] = s;
        __syncthreads();
        if (tid == 0) {
            float tt = 0.f;
#pragma unroll
            for (int i = 0; i < 8; ++i) tt += red8[i];
            out[loss_pos] = tt * (1.25f / (float)(F_ * B_ * D_));
            g_count = 0;
            g_tile  = 0;     // reset for next graph replay
        }
    }
}

// ---------------------------------------------------------------------------
extern "C" void kernel_launch(void* const* d_in, const int* in_sizes, int n_in,
                              void* d_out, int out_size) {
    const float* x = (const float*)d_in[0];   // (F,B,D)
    const float* w = (const float*)d_in[1];   // (F,D,K)
    float* out = (float*)d_out;

    cudaFuncSetAttribute(vq_main, cudaFuncAttributeMaxDynamicSharedMemorySize,
                         SMEM_BYTES);

    dim3 pgrid(16, 32);
    vq_prep<<<pgrid, 256>>>(w);

    vq_main<<<NCTAS, NTHREADS, SMEM_BYTES>>>(x, out, out_size - 1);
}